// round 2
// baseline (speedup 1.0000x reference)
#include <cuda_runtime.h>
#include <math.h>

#define BB 4
#define CC 64
#define NN 4096
#define HHD 64
#define AHD 256
#define KK 16
#define RS 20   // padded row stride for k-dim smem arrays (16 -> 20 floats, keeps 16B alignment, kills bank conflicts)

// ---------------- scratch (no allocations allowed) ----------------
__device__ float g_val_t[BB * NN * CC];   // y1 (value), layout (B,N,C)
__device__ float g_key_t[BB * NN * CC];   // key, layout (B,N,C)
__device__ float g_agg[BB * NN * CC];     // aggregated features, layout (B,N,C)
__device__ int   g_idx[BB * NN * KK];     // knn indices

typedef unsigned long long ull;

__device__ __forceinline__ ull pack2(float v) {
    ull r;
    asm("mov.b64 %0, {%1, %1};" : "=l"(r) : "f"(v));
    return r;
}
__device__ __forceinline__ void fma2(ull& acc, ull a, ull b) {
    asm("fma.rn.f32x2 %0, %1, %2, %0;" : "+l"(acc) : "l"(a), "l"(b));
}
__device__ __forceinline__ float2 unpack2(ull v) {
    float2 f;
    asm("mov.b64 {%0, %1}, %2;" : "=f"(f.x), "=f"(f.y) : "l"(v));
    return f;
}

// ================= Kernel 1: y1 = W_start@y+b ; key = W_key@y1+b (both written transposed (B,N,C)) =================
__global__ __launch_bounds__(256) void k_linear_start_key(
    const float* __restrict__ y,
    const float* __restrict__ Ws_g, const float* __restrict__ bs_g,
    const float* __restrict__ Wk_g, const float* __restrict__ bk_g)
{
    __shared__ float ys[64][64];
    __shared__ float y1s[64][64];
    __shared__ float Ws[64][64];
    int b = blockIdx.y, n0 = blockIdx.x * 64, t = threadIdx.x;

#pragma unroll
    for (int i = 0; i < 16; i++) { int e = t + i * 256; Ws[e >> 6][e & 63] = Ws_g[e]; }
#pragma unroll
    for (int i = 0; i < 16; i++) {
        int e = t + i * 256; int c = e >> 6, p = e & 63;
        ys[c][p] = y[((size_t)b * CC + c) * NN + n0 + p];
    }
    __syncthreads();

    int p = t & 63, og = t >> 6;
    float acc[16];
#pragma unroll
    for (int i = 0; i < 16; i++) acc[i] = bs_g[og * 16 + i];
#pragma unroll 4
    for (int c = 0; c < 64; c++) {
        float yv = ys[c][p];
#pragma unroll
        for (int i = 0; i < 16; i++) acc[i] = fmaf(Ws[og * 16 + i][c], yv, acc[i]);
    }
#pragma unroll
    for (int i = 0; i < 16; i++) y1s[og * 16 + i][p] = acc[i];
    {
        float4* vo = (float4*)&g_val_t[(((size_t)b * NN) + n0 + p) * CC + og * 16];
        vo[0] = make_float4(acc[0], acc[1], acc[2], acc[3]);
        vo[1] = make_float4(acc[4], acc[5], acc[6], acc[7]);
        vo[2] = make_float4(acc[8], acc[9], acc[10], acc[11]);
        vo[3] = make_float4(acc[12], acc[13], acc[14], acc[15]);
    }
    __syncthreads();
#pragma unroll
    for (int i = 0; i < 16; i++) { int e = t + i * 256; Ws[e >> 6][e & 63] = Wk_g[e]; }
    __syncthreads();
#pragma unroll
    for (int i = 0; i < 16; i++) acc[i] = bk_g[og * 16 + i];
#pragma unroll 4
    for (int c = 0; c < 64; c++) {
        float yv = y1s[c][p];
#pragma unroll
        for (int i = 0; i < 16; i++) acc[i] = fmaf(Ws[og * 16 + i][c], yv, acc[i]);
    }
    {
        float4* ko = (float4*)&g_key_t[(((size_t)b * NN) + n0 + p) * CC + og * 16];
        ko[0] = make_float4(acc[0], acc[1], acc[2], acc[3]);
        ko[1] = make_float4(acc[4], acc[5], acc[6], acc[7]);
        ko[2] = make_float4(acc[8], acc[9], acc[10], acc[11]);
        ko[3] = make_float4(acc[12], acc[13], acc[14], acc[15]);
    }
}

// ================= Kernel 2: KNN, warp-per-split (4 splits of 1024 candidates), then merge =================
__global__ __launch_bounds__(128) void k_knn(const float* __restrict__ x)
{
    __shared__ float4 cand[4][32];
    __shared__ float md[32][4][16];
    __shared__ int   mi[32][4][16];
    int b = blockIdx.y;
    int q0 = blockIdx.x * 32;
    int w = threadIdx.x >> 5, lane = threadIdx.x & 31;
    int i = q0 + lane;
    const float* xb = x + (size_t)b * 3 * NN;
    float qx = xb[i], qy = xb[NN + i], qz = xb[2 * NN + i];
    float qsq = qx * qx + qy * qy + qz * qz;

    float bd[16]; int bi[16];
#pragma unroll
    for (int s = 0; s < 16; s++) { bd[s] = 3.0e38f; bi[s] = 0; }

    int base = w * 1024;
    for (int c0 = 0; c0 < 1024; c0 += 32) {
        int j = base + c0 + lane;
        float a0 = xb[j], a1 = xb[NN + j], a2 = xb[2 * NN + j];
        cand[w][lane] = make_float4(a0, a1, a2, a0 * a0 + a1 * a1 + a2 * a2);
        __syncwarp();
#pragma unroll 4
        for (int jj = 0; jj < 32; jj++) {
            float4 cv = cand[w][jj];
            float dot = qx * cv.x + qy * cv.y + qz * cv.z;
            float d = qsq - 2.0f * dot + cv.w;
            if (d < bd[15]) {
                bd[15] = d; bi[15] = base + c0 + jj;
#pragma unroll
                for (int s = 15; s > 0; --s) {
                    if (bd[s] < bd[s - 1]) {
                        float td = bd[s]; bd[s] = bd[s - 1]; bd[s - 1] = td;
                        int ti = bi[s]; bi[s] = bi[s - 1]; bi[s - 1] = ti;
                    } else break;
                }
            }
        }
        __syncwarp();
    }
#pragma unroll
    for (int s = 0; s < 16; s++) { md[lane][w][s] = bd[s]; mi[lane][w][s] = bi[s]; }
    __syncthreads();

    if (threadIdx.x < 32) {
        int q = threadIdx.x;
#pragma unroll
        for (int s = 0; s < 16; s++) { bd[s] = md[q][0][s]; bi[s] = mi[q][0][s]; }
#pragma unroll
        for (int sp = 1; sp < 4; sp++) {
            for (int s = 0; s < 16; s++) {
                float d = md[q][sp][s];
                if (d >= bd[15]) break;     // lists sorted ascending
                bd[15] = d; bi[15] = mi[q][sp][s];
#pragma unroll
                for (int u = 15; u > 0; --u) {
                    if (bd[u] < bd[u - 1]) {
                        float td = bd[u]; bd[u] = bd[u - 1]; bd[u - 1] = td;
                        int ti = bi[u]; bi[u] = bi[u - 1]; bi[u - 1] = ti;
                    } else break;
                }
            }
        }
#pragma unroll
        for (int s = 0; s < 16; s++) g_idx[((size_t)b * NN + q0 + q) * KK + s] = bi[s];
    }
}

// ================= Kernel 3: fused pe + attention MLP + softmax + aggregation =================
struct __align__(16) S3 {
    float A1s[64][257];     // [c][a], BN-folded A1
    float A2s[256][65];     // [h][c]
    float P2s[64][65];      // [h][c]
    float P1p[64][3];       // BN-folded P1
    float Wq[64][3];
    float b1p[256];         // folded bias after A1+bn2
    float s2s[256];
    float pb1p[64];         // folded bias after P1+bn1
    float s1s[64];
    float pb2s[64];
    float ab2s[64];
    float bqs[64];
    float posr[2][3][16];
    float qy[2][64];
    float vals[2][64];
    float kgu[2][64][RS];   // gathered key, then u = (q-key)+pe in place
    float th[2][64][RS];    // pe hidden, then attn logits
    float pes[2][64][RS];
    float h1s[2][256][RS];
};

__global__ void __launch_bounds__(256, 1) k_attn(
    const float* __restrict__ x,
    const float* __restrict__ Wq_g, const float* __restrict__ bq_g,
    const float* __restrict__ P1, const float* __restrict__ pb1,
    const float* __restrict__ bn1_g, const float* __restrict__ bn1_b,
    const float* __restrict__ bn1_m, const float* __restrict__ bn1_v,
    const float* __restrict__ P2, const float* __restrict__ pb2,
    const float* __restrict__ A1, const float* __restrict__ ab1,
    const float* __restrict__ bn2_g, const float* __restrict__ bn2_b,
    const float* __restrict__ bn2_m, const float* __restrict__ bn2_v,
    const float* __restrict__ A2, const float* __restrict__ ab2)
{
    extern __shared__ char smraw[];
    S3& s = *(S3*)smraw;
    int t = threadIdx.x;
    int b = blockIdx.x >> 9;               // 512 tiles of 8 points per batch
    int n_base = (blockIdx.x & 511) * 8;

    // ---- fold BN into weights/biases, stage weights to smem ----
    {
        float s2 = bn2_g[t] / sqrtf(bn2_v[t] + 1e-5f);
        s.s2s[t] = s2;
        s.b1p[t] = (ab1[t] - bn2_m[t]) * s2 + bn2_b[t];
    }
    if (t < 64) {
        float s1 = bn1_g[t] / sqrtf(bn1_v[t] + 1e-5f);
        s.s1s[t] = s1;
        s.pb1p[t] = (pb1[t] - bn1_m[t]) * s1 + bn1_b[t];
        s.pb2s[t] = pb2[t];
        s.ab2s[t] = ab2[t];
        s.bqs[t] = bq_g[t];
    }
    if (t < 192) s.Wq[t / 3][t % 3] = Wq_g[t];
    __syncthreads();
    if (t < 192) s.P1p[t / 3][t % 3] = P1[t] * s.s1s[t / 3];
#pragma unroll
    for (int i = 0; i < 64; i++) { int e = t + i * 256; int a = e >> 6, c = e & 63; s.A1s[c][a] = A1[e] * s.s2s[a]; }
#pragma unroll
    for (int i = 0; i < 64; i++) { int e = t + i * 256; int c = e >> 8, h = e & 255; s.A2s[h][c] = A2[e]; }
#pragma unroll
    for (int i = 0; i < 16; i++) { int e = t + i * 256; int c = e >> 6, h = e & 63; s.P2s[h][c] = P2[e]; }
    __syncthreads();

    const float* xb = x + (size_t)b * 3 * NN;
    const int* idxb = &g_idx[(size_t)b * NN * KK];

    for (int pp = 0; pp < 8; pp += 2) {
        int n0 = n_base + pp;

        // ---- stage 0: gathers / small linears (idx read straight from global, L1-resident) ----
        if (t < 96) {
            int pt = t / 48, r = t % 48, d = r >> 4, k = r & 15;
            int j = idxb[(n0 + pt) * KK + k];
            s.posr[pt][d][k] = xb[d * NN + n0 + pt] - xb[d * NN + j];
        } else if (t >= 128) {
            int tt = t - 128, pt = tt >> 6, c = tt & 63;
            int n = n0 + pt;
            s.qy[pt][c] = s.bqs[c] + s.Wq[c][0] * xb[n] + s.Wq[c][1] * xb[NN + n] + s.Wq[c][2] * xb[2 * NN + n];
        }
        if (t < 128) {
            int pt = t >> 6, c = t & 63;
            s.vals[pt][c] = g_val_t[((size_t)b * NN + n0 + pt) * CC + c];
        }
        {   // gather key rows (contiguous 256B per neighbor in transposed layout)
            int pt = t >> 7, r = t & 127, c8 = r >> 4, k = r & 15;
            int j = idxb[(n0 + pt) * KK + k];
            const float4* kp = (const float4*)&g_key_t[((size_t)b * NN + j) * CC + c8 * 8];
            float4 v0 = kp[0], v1 = kp[1];
            int cb = c8 * 8;
            s.kgu[pt][cb + 0][k] = v0.x; s.kgu[pt][cb + 1][k] = v0.y;
            s.kgu[pt][cb + 2][k] = v0.z; s.kgu[pt][cb + 3][k] = v0.w;
            s.kgu[pt][cb + 4][k] = v1.x; s.kgu[pt][cb + 5][k] = v1.y;
            s.kgu[pt][cb + 6][k] = v1.z; s.kgu[pt][cb + 7][k] = v1.w;
        }
        __syncthreads();

        // ---- stage 1: th = relu(bn(P1@pos_rel + pb1))  (folded) ----
        {
            int h = t & 63, kg = t >> 6;
#pragma unroll
            for (int pt = 0; pt < 2; pt++) {
                float4 o;
                float* ov = (float*)&o;
#pragma unroll
                for (int kk = 0; kk < 4; kk++) {
                    int k = kg * 4 + kk;
                    float a = s.pb1p[h]
                            + s.P1p[h][0] * s.posr[pt][0][k]
                            + s.P1p[h][1] * s.posr[pt][1][k]
                            + s.P1p[h][2] * s.posr[pt][2][k];
                    ov[kk] = fmaxf(a, 0.0f);
                }
                *(float4*)&s.th[pt][h][kg * 4] = o;
            }
        }
        __syncthreads();

        // ---- stage 2+3: pe = P2 @ th + pb2 ; u = (query - key) + pe  (FFMA2) ----
        {
            int c = t & 63, kg = t >> 6;
            ull pbp = pack2(s.pb2s[c]);
            ull P00 = pbp, P01 = pbp, P10 = pbp, P11 = pbp;
#pragma unroll 4
            for (int h = 0; h < 64; h++) {
                ull w2 = pack2(s.P2s[h][c]);
                ulonglong2 t0 = *(const ulonglong2*)&s.th[0][h][kg * 4];
                ulonglong2 t1 = *(const ulonglong2*)&s.th[1][h][kg * 4];
                fma2(P00, w2, t0.x); fma2(P01, w2, t0.y);
                fma2(P10, w2, t1.x); fma2(P11, w2, t1.y);
            }
            float2 e00 = unpack2(P00), e01 = unpack2(P01);
            float2 e10 = unpack2(P10), e11 = unpack2(P11);
            float4 pe0 = make_float4(e00.x, e00.y, e01.x, e01.y);
            float4 pe1 = make_float4(e10.x, e10.y, e11.x, e11.y);
            *(float4*)&s.pes[0][c][kg * 4] = pe0;
            *(float4*)&s.pes[1][c][kg * 4] = pe1;
            float q0 = s.qy[0][c], q1 = s.qy[1][c];
            float4 kv0 = *(const float4*)&s.kgu[0][c][kg * 4];
            float4 kv1 = *(const float4*)&s.kgu[1][c][kg * 4];
            float4 u0, u1;
            u0.x = (q0 - kv0.x) + pe0.x; u0.y = (q0 - kv0.y) + pe0.y;
            u0.z = (q0 - kv0.z) + pe0.z; u0.w = (q0 - kv0.w) + pe0.w;
            u1.x = (q1 - kv1.x) + pe1.x; u1.y = (q1 - kv1.y) + pe1.y;
            u1.z = (q1 - kv1.z) + pe1.z; u1.w = (q1 - kv1.w) + pe1.w;
            *(float4*)&s.kgu[0][c][kg * 4] = u0;
            *(float4*)&s.kgu[1][c][kg * 4] = u1;
        }
        __syncthreads();

        // ---- stage 4: h1 = relu(A1' @ u + b1')  (FFMA2, one a-row per thread, 16 pair-accumulators) ----
        {
            int a = t;
            ull bb2 = pack2(s.b1p[a]);
            ull ac0[8], ac1[8];
#pragma unroll
            for (int j = 0; j < 8; j++) { ac0[j] = bb2; ac1[j] = bb2; }
#pragma unroll 2
            for (int c = 0; c < 64; c++) {
                ull w2 = pack2(s.A1s[c][a]);
                const ulonglong2* u0p = (const ulonglong2*)&s.kgu[0][c][0];
                const ulonglong2* u1p = (const ulonglong2*)&s.kgu[1][c][0];
#pragma unroll
                for (int g = 0; g < 4; g++) {
                    ulonglong2 u0 = u0p[g], u1 = u1p[g];
                    fma2(ac0[2 * g], w2, u0.x); fma2(ac0[2 * g + 1], w2, u0.y);
                    fma2(ac1[2 * g], w2, u1.x); fma2(ac1[2 * g + 1], w2, u1.y);
                }
            }
#pragma unroll
            for (int g = 0; g < 4; g++) {
                float2 v0 = unpack2(ac0[2 * g]), v1 = unpack2(ac0[2 * g + 1]);
                *(float4*)&s.h1s[0][a][g * 4] = make_float4(
                    fmaxf(v0.x, 0.0f), fmaxf(v0.y, 0.0f), fmaxf(v1.x, 0.0f), fmaxf(v1.y, 0.0f));
                float2 w0 = unpack2(ac1[2 * g]), w1 = unpack2(ac1[2 * g + 1]);
                *(float4*)&s.h1s[1][a][g * 4] = make_float4(
                    fmaxf(w0.x, 0.0f), fmaxf(w0.y, 0.0f), fmaxf(w1.x, 0.0f), fmaxf(w1.y, 0.0f));
            }
        }
        __syncthreads();

        // ---- stage 5: attn logits = A2 @ h1 + ab2 (FFMA2, into th) ----
        {
            int c = t & 63, kg = t >> 6;
            ull abp = pack2(s.ab2s[c]);
            ull A00 = abp, A01 = abp, A10 = abp, A11 = abp;
#pragma unroll 4
            for (int h = 0; h < 256; h++) {
                ull w2 = pack2(s.A2s[h][c]);
                ulonglong2 h0 = *(const ulonglong2*)&s.h1s[0][h][kg * 4];
                ulonglong2 h1 = *(const ulonglong2*)&s.h1s[1][h][kg * 4];
                fma2(A00, w2, h0.x); fma2(A01, w2, h0.y);
                fma2(A10, w2, h1.x); fma2(A11, w2, h1.y);
            }
            float2 e00 = unpack2(A00), e01 = unpack2(A01);
            float2 e10 = unpack2(A10), e11 = unpack2(A11);
            *(float4*)&s.th[0][c][kg * 4] = make_float4(e00.x, e00.y, e01.x, e01.y);
            *(float4*)&s.th[1][c][kg * 4] = make_float4(e10.x, e10.y, e11.x, e11.y);
        }
        __syncthreads();

        // ---- stage 6: softmax over k + aggregate + write (256 threads, half-k split + shfl) ----
        {
            int pt = t >> 7, r = t & 127, c = r >> 1, half = t & 1;
            float4 v0 = *(const float4*)&s.th[pt][c][half * 8];
            float4 v1 = *(const float4*)&s.th[pt][c][half * 8 + 4];
            float av[8] = {v0.x, v0.y, v0.z, v0.w, v1.x, v1.y, v1.z, v1.w};
            float m = av[0];
#pragma unroll
            for (int k = 1; k < 8; k++) m = fmaxf(m, av[k]);
            m = fmaxf(m, __shfl_xor_sync(0xFFFFFFFFu, m, 1));
            float vv = s.vals[pt][c];
            float vsum = 0.0f, acc = 0.0f;
#pragma unroll
            for (int k = 0; k < 8; k++) {
                float e = __expf(av[k] - m);
                vsum += e;
                acc = fmaf(e, vv + s.pes[pt][c][half * 8 + k], acc);
            }
            vsum += __shfl_xor_sync(0xFFFFFFFFu, vsum, 1);
            acc  += __shfl_xor_sync(0xFFFFFFFFu, acc, 1);
            if (half == 0) g_agg[((size_t)b * NN + n0 + pt) * CC + c] = acc / vsum;
        }
        __syncthreads();
    }
}

// ================= Kernel 4: out = W_end @ agg + b_end + y =================
__global__ __launch_bounds__(256) void k_end(
    const float* __restrict__ y, const float* __restrict__ We_g,
    const float* __restrict__ be_g, float* __restrict__ out)
{
    __shared__ float As[64][65];
    __shared__ float Ws[64][64];
    int b = blockIdx.y, n0 = blockIdx.x * 64, t = threadIdx.x;
#pragma unroll
    for (int i = 0; i < 16; i++) { int e = t + i * 256; Ws[e >> 6][e & 63] = We_g[e]; }
#pragma unroll
    for (int i = 0; i < 16; i++) {
        int e = t + i * 256; int p = e >> 6, c = e & 63;
        As[p][c] = g_agg[((size_t)b * NN + n0 + p) * CC + c];
    }
    __syncthreads();
    int p = t & 63, og = t >> 6;
    float acc[16];
#pragma unroll
    for (int i = 0; i < 16; i++) acc[i] = be_g[og * 16 + i];
#pragma unroll 4
    for (int c = 0; c < 64; c++) {
        float av = As[p][c];
#pragma unroll
        for (int i = 0; i < 16; i++) acc[i] = fmaf(Ws[og * 16 + i][c], av, acc[i]);
    }
#pragma unroll
    for (int i = 0; i < 16; i++) {
        int o = og * 16 + i;
        size_t off = ((size_t)b * CC + o) * NN + n0 + p;
        out[off] = acc[i] + y[off];
    }
}

// ================= launcher =================
extern "C" void kernel_launch(void* const* d_in, const int* in_sizes, int n_in,
                              void* d_out, int out_size)
{
    const float* x       = (const float*)d_in[0];
    const float* y       = (const float*)d_in[1];
    const float* W_start = (const float*)d_in[2];
    const float* b_start = (const float*)d_in[3];
    const float* W_key   = (const float*)d_in[4];
    const float* b_key   = (const float*)d_in[5];
    const float* W_query = (const float*)d_in[6];
    const float* b_query = (const float*)d_in[7];
    const float* P1      = (const float*)d_in[8];
    const float* pb1     = (const float*)d_in[9];
    const float* bn1_g   = (const float*)d_in[10];
    const float* bn1_b   = (const float*)d_in[11];
    const float* bn1_m   = (const float*)d_in[12];
    const float* bn1_v   = (const float*)d_in[13];
    const float* P2      = (const float*)d_in[14];
    const float* pb2     = (const float*)d_in[15];
    const float* A1      = (const float*)d_in[16];
    const float* ab1     = (const float*)d_in[17];
    const float* bn2_g   = (const float*)d_in[18];
    const float* bn2_b   = (const float*)d_in[19];
    const float* bn2_m   = (const float*)d_in[20];
    const float* bn2_v   = (const float*)d_in[21];
    const float* A2      = (const float*)d_in[22];
    const float* ab2     = (const float*)d_in[23];
    const float* W_end   = (const float*)d_in[24];
    const float* b_end   = (const float*)d_in[25];

    cudaFuncSetAttribute(k_attn, cudaFuncAttributeMaxDynamicSharedMemorySize, (int)sizeof(S3));

    k_linear_start_key<<<dim3(NN / 64, BB), 256>>>(y, W_start, b_start, W_key, b_key);
    k_knn<<<dim3(NN / 32, BB), 128>>>(x);
    k_attn<<<BB * NN / 8, 256, sizeof(S3)>>>(x, W_query, b_query,
                                             P1, pb1, bn1_g, bn1_b, bn1_m, bn1_v,
                                             P2, pb2, A1, ab1,
                                             bn2_g, bn2_b, bn2_m, bn2_v, A2, ab2);
    k_end<<<dim3(NN / 64, BB), 256>>>(y, W_end, b_end, (float*)d_out);
}